// round 13
// baseline (speedup 1.0000x reference)
#include <cuda_runtime.h>

// Positional encoding: out[n, c, {sin,cos}, d] = trig(x[n,c] * 2^d), d=0..9, c=0..2.
// Row = 60 f32 = 15 float4. Grid-stride loop, stride % 15 == 0 so the slot
// decomposition (t mod 15) is loop-invariant. Unrolled x2. A/B vs R8: plain
// global stores instead of __stcs -- let L2 act as a write-coalescing buffer
// for the 480MB stream instead of forcing evict-streaming.

#define HALF_PI 1.57079632679489662f

__global__ void __launch_bounds__(256) pe_kernel(const float* __restrict__ x,
                                                 float4* __restrict__ out,
                                                 int total /* N*15 */,
                                                 int stride /* gridDim*blockDim, %15==0 */) {
    int t0 = blockIdx.x * blockDim.x + threadIdx.x;

    // Loop-invariant slot decomposition.
    int k = t0 % 15;       // float4 slot within row
    int c = k / 5;         // channel 0..2
    int j = k - c * 5;     // float4 within channel block

    float scale[4], off[4];
#pragma unroll
    for (int m = 0; m < 4; ++m) {
        int r = 4 * j + m;              // 0..19 within channel block
        int iscos = (r >= 10) ? 1 : 0;  // first 10 sin, last 10 cos
        int d = r - 10 * iscos;         // frequency exponent 0..9
        scale[m] = __int_as_float((127 + d) << 23);  // exact 2^d
        off[m] = iscos ? HALF_PI : 0.0f;             // cos(p) = sin(p + pi/2)
    }

    int xi = (t0 / 15) * 3 + c;          // x index for slot t
    const int xstep = (stride / 15) * 3; // x advance per `stride` slots
    const int stride2 = 2 * stride;
    const int xstep2 = 2 * xstep;

    int t = t0;
    // Main loop: two slots per iteration (same k), batched loads then batched stores.
    for (; t + stride < total; t += stride2, xi += xstep2) {
        float xa = __ldg(&x[xi]);
        float xb = __ldg(&x[xi + xstep]);

        float4 va, vb;
        va.x = __sinf(fmaf(xa, scale[0], off[0]));
        va.y = __sinf(fmaf(xa, scale[1], off[1]));
        va.z = __sinf(fmaf(xa, scale[2], off[2]));
        va.w = __sinf(fmaf(xa, scale[3], off[3]));
        vb.x = __sinf(fmaf(xb, scale[0], off[0]));
        vb.y = __sinf(fmaf(xb, scale[1], off[1]));
        vb.z = __sinf(fmaf(xb, scale[2], off[2]));
        vb.w = __sinf(fmaf(xb, scale[3], off[3]));

        out[t] = va;              // plain store (default cache policy)
        out[t + stride] = vb;
    }
    // Tail: at most one remaining slot for this thread.
    if (t < total) {
        float xv = __ldg(&x[xi]);
        float4 v;
        v.x = __sinf(fmaf(xv, scale[0], off[0]));
        v.y = __sinf(fmaf(xv, scale[1], off[1]));
        v.z = __sinf(fmaf(xv, scale[2], off[2]));
        v.w = __sinf(fmaf(xv, scale[3], off[3]));
        out[t] = v;
    }
}

extern "C" void kernel_launch(void* const* d_in, const int* in_sizes, int n_in,
                              void* d_out, int out_size) {
    const float* x = (const float*)d_in[0];
    float4* out = (float4*)d_out;
    int n_rows = in_sizes[0] / 3;   // x is [N, 3]
    int total = n_rows * 15;        // float4 slots

    const int threads = 256;
    // blocks must be a multiple of 15 so stride % 15 == 0.
    // 1110 = 148 SMs * 7.5 -> ~7-8 blocks/SM, ~53 unrolled iterations per thread.
    int blocks = 1110;
    int stride = blocks * threads;
    pe_kernel<<<blocks, threads>>>(x, out, total, stride);
}

// round 16
// speedup vs baseline: 1.0397x; 1.0397x over previous
#include <cuda_runtime.h>

// Positional encoding: out[n, c, {sin,cos}, d] = trig(x[n,c] * 2^d), d=0..9, c=0..2.
// Row = 60 f32 = 15 float4. Grid-stride loop, stride % 15 == 0 so the slot
// decomposition (t mod 15) is loop-invariant. Unrolled x2 (loop step 2*stride,
// both slots share the same k): batch 2 LDGs -> compute -> 2 back-to-back STG.128.
// Champion config: measured 86.5us twice (R8, R10), ~5.1 TB/s -- at the
// effective HBM write-stream ceiling for this 480MB f32 output (SM pipes <=20%).

#define HALF_PI 1.57079632679489662f

__global__ void __launch_bounds__(256) pe_kernel(const float* __restrict__ x,
                                                 float4* __restrict__ out,
                                                 int total /* N*15 */,
                                                 int stride /* gridDim*blockDim, %15==0 */) {
    int t0 = blockIdx.x * blockDim.x + threadIdx.x;

    // Loop-invariant slot decomposition.
    int k = t0 % 15;       // float4 slot within row
    int c = k / 5;         // channel 0..2
    int j = k - c * 5;     // float4 within channel block

    float scale[4], off[4];
#pragma unroll
    for (int m = 0; m < 4; ++m) {
        int r = 4 * j + m;              // 0..19 within channel block
        int iscos = (r >= 10) ? 1 : 0;  // first 10 sin, last 10 cos
        int d = r - 10 * iscos;         // frequency exponent 0..9
        scale[m] = __int_as_float((127 + d) << 23);  // exact 2^d
        off[m] = iscos ? HALF_PI : 0.0f;             // cos(p) = sin(p + pi/2)
    }

    int xi = (t0 / 15) * 3 + c;          // x index for slot t
    const int xstep = (stride / 15) * 3; // x advance per `stride` slots
    const int stride2 = 2 * stride;
    const int xstep2 = 2 * xstep;

    int t = t0;
    // Main loop: two slots per iteration (same k), batched loads then batched stores.
    for (; t + stride < total; t += stride2, xi += xstep2) {
        float xa = __ldg(&x[xi]);
        float xb = __ldg(&x[xi + xstep]);

        float4 va, vb;
        va.x = __sinf(fmaf(xa, scale[0], off[0]));
        va.y = __sinf(fmaf(xa, scale[1], off[1]));
        va.z = __sinf(fmaf(xa, scale[2], off[2]));
        va.w = __sinf(fmaf(xa, scale[3], off[3]));
        vb.x = __sinf(fmaf(xb, scale[0], off[0]));
        vb.y = __sinf(fmaf(xb, scale[1], off[1]));
        vb.z = __sinf(fmaf(xb, scale[2], off[2]));
        vb.w = __sinf(fmaf(xb, scale[3], off[3]));

        __stcs(&out[t], va);
        __stcs(&out[t + stride], vb);
    }
    // Tail: at most one remaining slot for this thread.
    if (t < total) {
        float xv = __ldg(&x[xi]);
        float4 v;
        v.x = __sinf(fmaf(xv, scale[0], off[0]));
        v.y = __sinf(fmaf(xv, scale[1], off[1]));
        v.z = __sinf(fmaf(xv, scale[2], off[2]));
        v.w = __sinf(fmaf(xv, scale[3], off[3]));
        __stcs(&out[t], v);
    }
}

extern "C" void kernel_launch(void* const* d_in, const int* in_sizes, int n_in,
                              void* d_out, int out_size) {
    const float* x = (const float*)d_in[0];
    float4* out = (float4*)d_out;
    int n_rows = in_sizes[0] / 3;   // x is [N, 3]
    int total = n_rows * 15;        // float4 slots

    const int threads = 256;
    // blocks must be a multiple of 15 so stride % 15 == 0.
    // 1110 = 148 SMs * 7.5 -> ~7-8 blocks/SM, ~53 unrolled iterations per thread.
    int blocks = 1110;
    int stride = blocks * threads;
    pe_kernel<<<blocks, threads>>>(x, out, total, stride);
}